// round 16
// baseline (speedup 1.0000x reference)
#include <cuda_runtime.h>
#include <math.h>
#include <stdint.h>

// Problem constants (B=4096, I=H=1024, 4H=4096)
#define MB 4096
#define KK 1024
#define NN 4096
#define HH 1024
#define MTOT 8192              // input rows stacked on h_prev rows

// ---------------- scratch (allocation-free: device globals) ----------------
// A' fragment-major: [mb(64)][ks(32)][mt(8)][kc(4)][lane(32)][j(4)] floats = 32 MB
__device__ __align__(1024) float g_Atf[(size_t)MTOT * KK];
// B' fragment-major: [mat][nb(16)][ks(32)][nt(32)][kc(4)][lane(32)][jb(2)] floats = 32 MB
__device__ __align__(1024) float g_Btf[2][(size_t)NN * KK];
__device__ float g_pre_i2h[(size_t)MB * NN];                               // 64 MB
__device__ float g_pre_h2h[(size_t)MB * NN];                               // 64 MB

// ========================= PTX helpers =========================
__device__ __forceinline__ uint32_t f2tf32(float x) {
    uint32_t r;
    asm("cvt.rna.tf32.f32 %0, %1;" : "=r"(r) : "f"(x));
    return r;
}
__device__ __forceinline__ void mma_tf32(float* d, uint32_t a0, uint32_t a1, uint32_t a2, uint32_t a3,
                                         uint32_t b0, uint32_t b1) {
    asm volatile("mma.sync.aligned.m16n8k8.row.col.f32.tf32.tf32.f32 "
        "{%0,%1,%2,%3}, {%4,%5,%6,%7}, {%8,%9}, {%0,%1,%2,%3};"
        : "+f"(d[0]), "+f"(d[1]), "+f"(d[2]), "+f"(d[3])
        : "r"(a0), "r"(a1), "r"(a2), "r"(a3), "r"(b0), "r"(b1));
}
__device__ __forceinline__ void ldg128(uint32_t* r, const float* p) {
    asm volatile("ld.global.ca.v4.b32 {%0,%1,%2,%3}, [%4];"
        : "=r"(r[0]), "=r"(r[1]), "=r"(r[2]), "=r"(r[3]) : "l"(p));
}
__device__ __forceinline__ void ldg64(uint32_t* r, const float* p) {
    asm volatile("ld.global.ca.v2.b32 {%0,%1}, [%2];"
        : "=r"(r[0]), "=r"(r[1]) : "l"(p));
}

// ========================= conversion kernels =========================
// A': one thread per (mb,ks,mt,kc,lane); writes its 4 fragment regs as float4.
// a0=A[m][k], a1=A[m+8][k], a2=A[m][k+4], a3=A[m+8][k+4]; m=mb*128+mt*16+(l>>2), k=ks*32+kc*8+(l&3)
__global__ __launch_bounds__(256)
void convert_A(const float* __restrict__ input, const float* __restrict__ h_prev)
{
    const uint32_t t = blockIdx.x * 256 + threadIdx.x;   // 0 .. 2^21-1
    const int l  = t & 31;
    const int kc = (t >> 5) & 3;
    const int mt = (t >> 7) & 7;
    const int ks = (t >> 10) & 31;
    const int mb = t >> 15;
    const int m = mb * 128 + mt * 16 + (l >> 2);
    const int k = ks * 32 + kc * 8 + (l & 3);
    const float* src = (m < MB) ? (input + (size_t)m * KK) : (h_prev + (size_t)(m - MB) * KK);
    const float* src8 = (m + 8 < MB) ? (input + (size_t)(m + 8) * KK) : (h_prev + (size_t)(m + 8 - MB) * KK);
    uint4 o;
    o.x = f2tf32(src[k]);
    o.y = f2tf32(src8[k]);
    o.z = f2tf32(src[k + 4]);
    o.w = f2tf32(src8[k + 4]);
    *reinterpret_cast<uint4*>(g_Atf + (size_t)t * 4) = o;
}

// B': one thread per (nb,ks,nt,kc,lane); writes b0,b1 as float2.
// b0=w[k][n], b1=w[k+4][n]; n=nb*256+nt*8+(l>>2), k=ks*32+kc*8+(l&3)
__global__ __launch_bounds__(256)
void convert_B(const float* __restrict__ w0, const float* __restrict__ w1)
{
    const uint32_t t = blockIdx.x * 256 + threadIdx.x;   // 0 .. 2^21-1
    const int mat = blockIdx.z;
    const float* w = mat ? w1 : w0;
    const int l  = t & 31;
    const int kc = (t >> 5) & 3;
    const int nt = (t >> 7) & 31;
    const int ks = (t >> 12) & 31;
    const int nb = t >> 17;
    const int n = nb * 256 + nt * 8 + (l >> 2);
    const int k = ks * 32 + kc * 8 + (l & 3);
    uint2 o;
    o.x = f2tf32(w[(size_t)k * NN + n]);
    o.y = f2tf32(w[(size_t)(k + 4) * NN + n]);
    *reinterpret_cast<uint2*>(g_Btf[mat] + (size_t)t * 2) = o;
}

// ========================= tf32 mma.sync GEMM (no smem: global->reg) ========
// C[128,256] tiles; operands pre-permuted in fragment-major order.
#define BM 128
#define BN 256
#define GTHREADS 256
#define NSLICES 128            // ks(32) x kc(4)

// Per kc-slice strides in floats:
// A: [ks][mt(8)][kc(4)][lane(32)][4]  -> slice (ks,kc): base + (ks*32 + kc)*... see below
// B: [ks][nt(32)][kc(4)][lane(32)][2]

__global__ __launch_bounds__(GTHREADS, 1)
void gemm_tf32()
{
    const int tid = threadIdx.x;
    const int wid = tid >> 5;
    const int lid = tid & 31;
    const int warp_m = wid >> 2;        // 0..1 -> 64-row slab (4 mtiles)
    const int warp_n = wid & 3;         // 0..3 -> 64-col slab (8 ntiles)

    const int tileN = blockIdx.x;       // 0..15
    const int tileM = blockIdx.y;       // 0..63
    const int mat = (tileM >= 32) ? 1 : 0;
    // A' per mb: 32 ks * 4096 floats; B' per nb: 32 ks * 8192 floats
    const float* gA = g_Atf + (size_t)tileM * 32 * 4096;
    const float* gB = g_Btf[mat] + (size_t)tileN * 32 * 8192;

    float acc[4][8][4];
    #pragma unroll
    for (int mi = 0; mi < 4; mi++)
        #pragma unroll
        for (int ni = 0; ni < 8; ni++)
            #pragma unroll
            for (int r = 0; r < 4; r++)
                acc[mi][ni][r] = 0.0f;

    // Per-thread base pointers for this warp's fragments.
    // A slice (ks,kc), mtile mt=warp_m*4+mi: offset = ((ks*8 + mt)*4 + kc)*128 + lid*4
    // B slice (ks,kc), ntile nt=warp_n*8+ni: offset = ((ks*32 + nt)*4 + kc)*64 + lid*2
    const float* aBase = gA + (size_t)(warp_m * 4) * 512 + lid * 4;   // mt stride = 4*128 = 512
    const float* bBase = gB + (size_t)(warp_n * 8) * 256 + lid * 2;   // nt stride = 4*64  = 256

    uint32_t a[2][4][4];
    uint32_t b[2][8][2];

    // prefetch slice 0 (ks=0, kc=0)
    #pragma unroll
    for (int mi = 0; mi < 4; mi++)
        ldg128(a[0][mi], aBase + mi * 512);
    #pragma unroll
    for (int ni = 0; ni < 8; ni++)
        ldg64(b[0][ni], bBase + ni * 256);

    for (int t = 0; t < NSLICES; t++) {
        const int cur = t & 1;
        const int nxt = cur ^ 1;
        if (t + 1 < NSLICES) {
            const int t1 = t + 1;
            const int ks1 = t1 >> 2;
            const int kc1 = t1 & 3;
            const float* aS = aBase + (size_t)ks1 * 4096 + kc1 * 128;
            const float* bS = bBase + (size_t)ks1 * 8192 + kc1 * 64;
            #pragma unroll
            for (int mi = 0; mi < 4; mi++)
                ldg128(a[nxt][mi], aS + mi * 512);
            #pragma unroll
            for (int ni = 0; ni < 8; ni++)
                ldg64(b[nxt][ni], bS + ni * 256);
        }
        #pragma unroll
        for (int mi = 0; mi < 4; mi++)
            #pragma unroll
            for (int ni = 0; ni < 8; ni++)
                mma_tf32(acc[mi][ni], a[cur][mi][0], a[cur][mi][1], a[cur][mi][2], a[cur][mi][3],
                         b[cur][ni][0], b[cur][ni][1]);
    }

    // store C (D layout: d0,d1 -> row lid>>2, cols (lid&3)*2,+1; d2,d3 -> row+8)
    float* gC = ((tileM < 32) ? (g_pre_i2h + (size_t)tileM * BM * NN)
                              : (g_pre_h2h + (size_t)(tileM - 32) * BM * NN))
                + (size_t)tileN * BN;
    const int mrow = warp_m * 64 + (lid >> 2);
    const int ncol = warp_n * 64 + (lid & 3) * 2;
    #pragma unroll
    for (int mi = 0; mi < 4; mi++) {
        #pragma unroll
        for (int ni = 0; ni < 8; ni++) {
            float* p0 = gC + (size_t)(mrow + mi * 16) * NN + ncol + ni * 8;
            float* p1 = gC + (size_t)(mrow + mi * 16 + 8) * NN + ncol + ni * 8;
            *reinterpret_cast<float2*>(p0) = make_float2(acc[mi][ni][0], acc[mi][ni][1]);
            *reinterpret_cast<float2*>(p1) = make_float2(acc[mi][ni][2], acc[mi][ni][3]);
        }
    }
}

// ========================= LN + gates epilogue =========================
#define EPS 1e-6f

__device__ __forceinline__ float sigm(float x) { return 1.0f / (1.0f + __expf(-x)); }
__device__ __forceinline__ float fast_tanh(float x) {
    float ax = fminf(fabsf(x), 15.0f);
    float t = __expf(2.0f * ax);
    float r = (t - 1.0f) / (t + 1.0f);
    return copysignf(r, x);
}

__device__ void block_reduce2(float& s, float& q)
{
    __shared__ __align__(16) float rs[8], rq[8];
    __shared__ float bs, bq;
    #pragma unroll
    for (int o = 16; o > 0; o >>= 1) {
        s += __shfl_down_sync(0xffffffffu, s, o);
        q += __shfl_down_sync(0xffffffffu, q, o);
    }
    const int w = threadIdx.x >> 5, l = threadIdx.x & 31;
    __syncthreads();
    if (l == 0) { rs[w] = s; rq[w] = q; }
    __syncthreads();
    if (threadIdx.x == 0) {
        float a = 0.0f, b = 0.0f;
        #pragma unroll
        for (int i = 0; i < 8; i++) { a += rs[i]; b += rq[i]; }
        bs = a; bq = b;
    }
    __syncthreads();
    s = bs; q = bq;
}

__global__ __launch_bounds__(256)
void lstm_epilogue(const float* __restrict__ c_prev,
                   const float* __restrict__ b_i2h, const float* __restrict__ b_h2h,
                   const float* __restrict__ g_i2h, const float* __restrict__ be_i2h,
                   const float* __restrict__ g_h2h, const float* __restrict__ be_h2h,
                   const float* __restrict__ g_c,   const float* __restrict__ be_c,
                   float* __restrict__ out)
{
    __shared__ __align__(16) float sh_g[NN];
    __shared__ __align__(16) float sh_h[NN];

    const int r = blockIdx.x;
    const int tid = threadIdx.x;
    const float* hi = g_pre_i2h + (size_t)r * NN;
    const float* hh = g_pre_h2h + (size_t)r * NN;

    float s = 0.0f, q = 0.0f;
    for (int j = tid * 4; j < NN; j += 1024) {
        float4 v = *reinterpret_cast<const float4*>(hi + j);
        float4 b = *reinterpret_cast<const float4*>(b_i2h + j);
        v.x += b.x; v.y += b.y; v.z += b.z; v.w += b.w;
        *reinterpret_cast<float4*>(sh_g + j) = v;
        s += v.x + v.y + v.z + v.w;
        q += v.x * v.x + v.y * v.y + v.z * v.z + v.w * v.w;
    }
    block_reduce2(s, q);
    const float m1 = s / (float)NN;
    const float v1 = (q - s * s / (float)NN) / (float)(NN - 1);
    const float inv1 = 1.0f / (sqrtf(v1) + EPS);

    s = 0.0f; q = 0.0f;
    for (int j = tid * 4; j < NN; j += 1024) {
        float4 v = *reinterpret_cast<const float4*>(hh + j);
        float4 b = *reinterpret_cast<const float4*>(b_h2h + j);
        v.x += b.x; v.y += b.y; v.z += b.z; v.w += b.w;
        *reinterpret_cast<float4*>(sh_h + j) = v;
        s += v.x + v.y + v.z + v.w;
        q += v.x * v.x + v.y * v.y + v.z * v.z + v.w * v.w;
    }
    block_reduce2(s, q);
    const float m2 = s / (float)NN;
    const float v2 = (q - s * s / (float)NN) / (float)(NN - 1);
    const float inv2 = 1.0f / (sqrtf(v2) + EPS);

    for (int j = tid * 4; j < NN; j += 1024) {
        float4 x = *reinterpret_cast<const float4*>(sh_g + j);
        float4 y = *reinterpret_cast<const float4*>(sh_h + j);
        float4 ga = *reinterpret_cast<const float4*>(g_i2h + j);
        float4 ba = *reinterpret_cast<const float4*>(be_i2h + j);
        float4 gb = *reinterpret_cast<const float4*>(g_h2h + j);
        float4 bb = *reinterpret_cast<const float4*>(be_h2h + j);
        float4 o;
        o.x = ga.x * ((x.x - m1) * inv1) + ba.x + gb.x * ((y.x - m2) * inv2) + bb.x;
        o.y = ga.y * ((x.y - m1) * inv1) + ba.y + gb.y * ((y.y - m2) * inv2) + bb.y;
        o.z = ga.z * ((x.z - m1) * inv1) + ba.z + gb.z * ((y.z - m2) * inv2) + bb.z;
        o.w = ga.w * ((x.w - m1) * inv1) + ba.w + gb.w * ((y.w - m2) * inv2) + bb.w;
        *reinterpret_cast<float4*>(sh_g + j) = o;
    }
    __syncthreads();

    s = 0.0f; q = 0.0f;
    for (int k = tid * 4; k < HH; k += 1024) {
        float4 ig = *reinterpret_cast<const float4*>(sh_g + k);
        float4 fg = *reinterpret_cast<const float4*>(sh_g + HH + k);
        float4 ug = *reinterpret_cast<const float4*>(sh_g + 2 * HH + k);
        float4 og = *reinterpret_cast<const float4*>(sh_g + 3 * HH + k);
        float4 cv = *reinterpret_cast<const float4*>(c_prev + (size_t)r * HH + k);
        float4 cp;
        cp.x = cv.x * sigm(fg.x + 1.0f) + fast_tanh(ug.x) * sigm(ig.x);
        cp.y = cv.y * sigm(fg.y + 1.0f) + fast_tanh(ug.y) * sigm(ig.y);
        cp.z = cv.z * sigm(fg.z + 1.0f) + fast_tanh(ug.z) * sigm(ig.z);
        cp.w = cv.w * sigm(fg.w + 1.0f) + fast_tanh(ug.w) * sigm(ig.w);
        *reinterpret_cast<float4*>(sh_h + k) = cp;
        *reinterpret_cast<float4*>(sh_h + HH + k) = og;
        s += cp.x + cp.y + cp.z + cp.w;
        q += cp.x * cp.x + cp.y * cp.y + cp.z * cp.z + cp.w * cp.w;
    }
    block_reduce2(s, q);
    const float m3 = s / (float)HH;
    const float v3 = (q - s * s / (float)HH) / (float)(HH - 1);
    const float inv3 = 1.0f / (sqrtf(v3) + EPS);

    float* out_h = out;
    float* out_c = out + (size_t)MB * HH;
    for (int k = tid * 4; k < HH; k += 1024) {
        float4 cp = *reinterpret_cast<const float4*>(sh_h + k);
        float4 og = *reinterpret_cast<const float4*>(sh_h + HH + k);
        float4 gc = *reinterpret_cast<const float4*>(g_c + k);
        float4 bc = *reinterpret_cast<const float4*>(be_c + k);
        float4 c, h;
        c.x = gc.x * ((cp.x - m3) * inv3) + bc.x;
        c.y = gc.y * ((cp.y - m3) * inv3) + bc.y;
        c.z = gc.z * ((cp.z - m3) * inv3) + bc.z;
        c.w = gc.w * ((cp.w - m3) * inv3) + bc.w;
        h.x = sigm(og.x) * fast_tanh(c.x);
        h.y = sigm(og.y) * fast_tanh(c.y);
        h.z = sigm(og.z) * fast_tanh(c.z);
        h.w = sigm(og.w) * fast_tanh(c.w);
        *reinterpret_cast<float4*>(out_h + (size_t)r * HH + k) = h;
        *reinterpret_cast<float4*>(out_c + (size_t)r * HH + k) = c;
    }
}

// ========================= launch =========================
extern "C" void kernel_launch(void* const* d_in, const int* in_sizes, int n_in,
                              void* d_out, int out_size)
{
    const float* input  = (const float*)d_in[0];
    const float* h_prev = (const float*)d_in[1];
    const float* c_prev = (const float*)d_in[2];
    const float* w_i2h  = (const float*)d_in[3];
    const float* b_i2h  = (const float*)d_in[4];
    const float* w_h2h  = (const float*)d_in[5];
    const float* b_h2h  = (const float*)d_in[6];
    const float* g_i2h  = (const float*)d_in[7];
    const float* be_i2h = (const float*)d_in[8];
    const float* g_h2h  = (const float*)d_in[9];
    const float* be_h2h = (const float*)d_in[10];
    const float* g_c    = (const float*)d_in[11];
    const float* be_c   = (const float*)d_in[12];
    float* out = (float*)d_out;

    // tf32 operand prep in mma fragment-major order
    convert_A<<<(MTOT / 16) * (KK / 8) / 8, 256>>>(input, h_prev);            // 8192 blocks
    convert_B<<<dim3((NN / 8) * (KK / 8) / 8, 1, 2), 256>>>(w_i2h, w_h2h);    // 8192 x 2 blocks

    // fused dual GEMM on tf32 HMMA, operands streamed global->reg (L2-resident)
    gemm_tf32<<<dim3(NN / BN, MTOT / BM), GTHREADS>>>();

    lstm_epilogue<<<MB, 256>>>(c_prev, b_i2h, b_h2h, g_i2h, be_i2h,
                               g_h2h, be_h2h, g_c, be_c, out);
}